// round 11
// baseline (speedup 1.0000x reference)
#include <cuda_runtime.h>
#include <math_constants.h>

#define NCLS 3
#define NBLOCKS 434

extern __shared__ float dynsmem[];

__device__ float g_scratch[4];        // zero-init; last block resets each run
__device__ unsigned int g_ticket;     // zero-init; last block resets each run

__device__ __forceinline__ float max3(float a, float b, float c) {
    return fmaxf(fmaxf(a, b), c);
}

// Block reduce of (lsum, csum) -> atomicAdd into g_scratch[o_loss], [o_cnt].
__device__ __forceinline__ void reduce_and_accumulate(float lsum, float csum,
                                                      int o_loss, int o_cnt)
{
    __shared__ float rl[16], rc[16];
    int lane = threadIdx.x & 31, warp = threadIdx.x >> 5;
    #pragma unroll
    for (int off = 16; off > 0; off >>= 1) {
        lsum += __shfl_down_sync(0xffffffffu, lsum, off);
        csum += __shfl_down_sync(0xffffffffu, csum, off);
    }
    if (lane == 0) { rl[warp] = lsum; rc[warp] = csum; }
    __syncthreads();
    if (warp == 0) {
        int nw = blockDim.x >> 5;
        lsum = (lane < nw) ? rl[lane] : 0.0f;
        csum = (lane < nw) ? rc[lane] : 0.0f;
        #pragma unroll
        for (int off = 16; off > 0; off >>= 1) {
            lsum += __shfl_down_sync(0xffffffffu, lsum, off);
            csum += __shfl_down_sync(0xffffffffu, csum, off);
        }
        if (lane == 0) {
            atomicAdd(&g_scratch[o_loss], lsum);
            atomicAdd(&g_scratch[o_cnt], csum);
        }
    }
}

// Negative branch for one (b, a, d-tile, h-tile). TW == W (full rows).
// smem holds SUM = 1 + e^{x1-x0} + e^{x2-x0} (log deferred; log monotonic ->
// 3x3x3 max and mp==center identical in sum domain). Halo pad = 0.0f.
template<int TD, int TH, int TW, int D, int H, int W, int A>
__device__ __forceinline__ void neg_level(const float* __restrict__ logit,
                                          const float* __restrict__ prob_gt,
                                          int local)
{
    constexpr int SD = TD + 2, SH = TH + 2;
    constexpr int SWP = (TW + 8 + 3) & ~3;     // 72 (TW=64), 40 (TW=32)
    constexpr int ROWS = SD * SH;
    constexpr int VEC = TW / 4;
    constexpr int ITEMS = ROWS * VEC;
    constexpr int NIT = (ITEMS + 511) / 512;
    constexpr int tilesD = D / TD, tilesH = H / TH;
    constexpr int S = D * H * W;
    constexpr int ODC = TD / 2;                // depth outputs per warp group

    float* s = dynsmem;

    const int baIdx = local / (tilesD * tilesH);
    const int tile  = local % (tilesD * tilesH);
    const int b = baIdx / A, a = baIdx % A;
    const int d0 = (tile / tilesH) * TD;
    const int h0 = (tile % tilesH) * TH;

    const float* l0 = logit + (b * NCLS * A + a) * S;
    const int tid = threadIdx.x;
    const float PAD = 0.0f;

    // ---- Phase 1: sum = 1 + e^{x1-x0} + e^{x2-x0}, float4, static unroll ----
    #pragma unroll
    for (int it = 0; it < NIT; it++) {
        int idx = tid + it * 512;
        if (NIT * 512 == ITEMS || idx < ITEMS) {
            int row = idx / VEC;
            int v   = idx & (VEC - 1);
            int dz = row / SH, hz = row % SH;
            int d = d0 + dz - 1, h = h0 + hz - 1;
            float4 r;
            if ((unsigned)d < (unsigned)D && (unsigned)h < (unsigned)H) {
                int sp = (d * H + h) * W + 4 * v;
                float4 a0 = __ldg((const float4*)(l0 + sp));
                float4 a1 = __ldg((const float4*)(l0 + A * S + sp));
                float4 a2 = __ldg((const float4*)(l0 + 2 * A * S + sp));
                r.x = 1.0f + __expf(a1.x - a0.x) + __expf(a2.x - a0.x);
                r.y = 1.0f + __expf(a1.y - a0.y) + __expf(a2.y - a0.y);
                r.z = 1.0f + __expf(a1.z - a0.z) + __expf(a2.z - a0.z);
                r.w = 1.0f + __expf(a1.w - a0.w) + __expf(a2.w - a0.w);
            } else {
                r.x = r.y = r.z = r.w = PAD;
            }
            *(float4*)(s + row * SWP + 4 + 4 * v) = r;
        }
    }
    __syncthreads();

    // ---- Phase 2: NMS in sum domain + focal neg loss (log deferred) ----
    const int lane = tid & 31, warp = tid >> 5;
    const int ty  = warp & 7;            // TH == 8 always
    const int tz  = warp >> 3;
    const int odb = tz * ODC;

    const float* pg = prob_gt + (b * A + a) * S;
    float lsum = 0.0f, csum = 0.0f;

    if (TW == 64) {
        // Each lane owns a w-pair (cols cp, cp+1) via 64-bit smem accesses.
        const int cp = 4 + 2 * lane;
        auto hw2 = [&](int z) -> float2 {
            const float* p = s + (z * SH + ty) * SWP + cp;
            float2 r0 = *(const float2*)p;
            float2 r1 = *(const float2*)(p + SWP);
            float2 r2 = *(const float2*)(p + 2 * SWP);
            float hx = max3(r0.x, r1.x, r2.x);
            float hy = max3(r0.y, r1.y, r2.y);
            float l = __shfl_up_sync(0xffffffffu, hy, 1);
            float r = __shfl_down_sync(0xffffffffu, hx, 1);
            if (lane == 0)  l = PAD;
            if (lane == 31) r = PAD;
            return make_float2(max3(l, hx, hy), max3(hx, hy, r));
        };
        float2 a0 = hw2(odb), a1 = hw2(odb + 1);
        #pragma unroll
        for (int i = 0; i < ODC; i++) {
            int od = odb + i;
            int gb = ((d0 + od) * H + h0 + ty) * W + cp - 4;
            float2 pgv = __ldg((const float2*)(pg + gb));   // hoisted
            float2 a2 = hw2(od + 2);
            float mpx = max3(a0.x, a1.x, a2.x);
            float mpy = max3(a0.y, a1.y, a2.y);
            float2 cen = *(const float2*)(s + ((od + 1) * SH + ty + 1) * SWP + cp);
            if (mpx == cen.x && pgv.x == -1.0f) {
                float nll = __logf(cen.x);
                float p = __expf(-nll);
                float q = 1.0f - p; float wn = q * q;
                lsum += nll * wn; csum += wn;
            }
            if (mpy == cen.y && pgv.y == -1.0f) {
                float nll = __logf(cen.y);
                float p = __expf(-nll);
                float q = 1.0f - p; float wn = q * q;
                lsum += nll * wn; csum += wn;
            }
            a0 = a1; a1 = a2;
        }
    } else {
        const int ca = 4 + lane;
        auto wm1 = [&](int z) -> float {
            const float* p = s + (z * SH + ty) * SWP + ca;
            float h = max3(p[0], p[SWP], p[2 * SWP]);
            float l = __shfl_up_sync(0xffffffffu, h, 1);
            float r = __shfl_down_sync(0xffffffffu, h, 1);
            if (lane == 0)  l = PAD;
            if (lane == 31) r = PAD;
            return max3(l, h, r);
        };
        float a0 = wm1(odb), a1 = wm1(odb + 1);
        #pragma unroll
        for (int i = 0; i < ODC; i++) {
            int od = odb + i;
            int gb = ((d0 + od) * H + h0 + ty) * W;
            float pga = __ldg(pg + gb + lane);
            float a2 = wm1(od + 2);
            float mp = max3(a0, a1, a2);
            float cen = s[((od + 1) * SH + ty + 1) * SWP + ca];
            if (mp == cen && pga == -1.0f) {
                float nll = __logf(cen);
                float p = __expf(-nll);
                float q = 1.0f - p; float wn = q * q;
                lsum += nll * wn; csum += wn;
            }
            a0 = a1; a1 = a2;
        }
    }
    reduce_and_accumulate(lsum, csum, 1, 3);
}

// Positive branch (one 512-thread block, B*P = 512 points).
__device__ __forceinline__ void pos_level(const float* __restrict__ logit,
                                          const float* __restrict__ prob_gt,
                                          const int* __restrict__ coord,
                                          const float* __restrict__ wcls,
                                          int A, int D, int H, int W, int P)
{
    int idx = threadIdx.x;
    float lsum = 0.0f, csum = 0.0f;
    int b = idx / P;
    int4 c = __ldg((const int4*)coord + idx);
    int a = c.x;
    if (a > -1) {
        int d = c.y, h = c.z, w = c.w;
        int S = D * H * W;
        int sp = (d * H + h) * W + w;
        int cls = (int)__ldg(prob_gt + (b * A + a) * S + sp);
        const float* lb = logit + (b * NCLS * A + a) * S + sp;
        float x0 = __ldg(lb);
        float x1 = __ldg(lb + A * S);
        float x2 = __ldg(lb + 2 * A * S);
        float m = fmaxf(x0, fmaxf(x1, x2));
        float lse = m + __logf(__expf(x0 - m) + __expf(x1 - m) + __expf(x2 - m));
        float xc = (cls == 0) ? x0 : ((cls == 1) ? x1 : x2);
        float nll = lse - xc;
        float pt = __expf(-nll);
        float q = 1.0f - pt;
        float wp = q * q * __ldg(wcls + cls);
        lsum = nll * wp;
        csum = wp;
    }
    __syncthreads();
    reduce_and_accumulate(lsum, csum, 0, 2);
}

// Blocks 0..383: level0 neg (16x8x64). 384..431: level1 neg (32x8x32 full-depth).
// Blocks 432, 433: positive branch. 434 <= 444 = 3*148 -> balanced single wave.
// Last finishing block copies g_scratch -> out and resets scratch (graph-safe).
__global__ void __launch_bounds__(512, 3)
mega_kernel(const float* __restrict__ logit0, const float* __restrict__ logit1,
            const float* __restrict__ pg0, const float* __restrict__ pg1,
            const int* __restrict__ c0, const int* __restrict__ c1,
            const float* __restrict__ wcls, float* __restrict__ out)
{
    int bx = blockIdx.x;
    if (bx < 384) {
        neg_level<16, 8, 64, 64, 64, 64, 3>(logit0, pg0, bx);
    } else if (bx < 432) {
        neg_level<32, 8, 32, 32, 32, 32, 3>(logit1, pg1, bx - 384);
    } else if (bx == 432) {
        pos_level(logit0, pg0, c0, wcls, 3, 64, 64, 64, 128);
    } else {
        pos_level(logit1, pg1, c1, wcls, 3, 32, 32, 32, 128);
    }

    // Finalize: tid 0 issued this block's scratch atomics (warp 0 lane 0).
    if (threadIdx.x == 0) {
        __threadfence();
        unsigned t = atomicAdd(&g_ticket, 1u);
        if (t == NBLOCKS - 1) {
            #pragma unroll
            for (int i = 0; i < 4; i++) {
                out[i] = atomicExch(&g_scratch[i], 0.0f);
            }
            atomicExch(&g_ticket, 0u);
        }
    }
}

extern "C" void kernel_launch(void* const* d_in, const int* in_sizes, int n_in,
                              void* d_out, int out_size)
{
    const float* logit0 = (const float*)d_in[0];
    const float* logit1 = (const float*)d_in[1];
    const float* pg0    = (const float*)d_in[2];
    const float* pg1    = (const float*)d_in[3];
    const int*   c0     = (const int*)d_in[4];
    const int*   c1     = (const int*)d_in[5];
    const float* wcls   = (const float*)d_in[6];
    float* out = (float*)d_out;

    // smem: max(level0 18*10*72, level1 34*10*40) floats = 13600 * 4 = 54400 B
    constexpr int SMEM_BYTES = 34 * 10 * 40 * 4;
    static bool attr_set = false;
    if (!attr_set) {
        cudaFuncSetAttribute(mega_kernel,
                             cudaFuncAttributeMaxDynamicSharedMemorySize,
                             SMEM_BYTES);
        attr_set = true;
    }

    mega_kernel<<<NBLOCKS, 512, SMEM_BYTES>>>(logit0, logit1, pg0, pg1,
                                              c0, c1, wcls, out);
}

// round 12
// speedup vs baseline: 1.0132x; 1.0132x over previous
#include <cuda_runtime.h>
#include <math_constants.h>

#define NCLS 3
#define NBLOCKS 434

extern __shared__ float dynsmem[];

__device__ float g_scratch[4];        // zero-init; last block resets each run
__device__ unsigned int g_ticket;     // zero-init; last block resets each run

__device__ __forceinline__ float max3(float a, float b, float c) {
    return fmaxf(fmaxf(a, b), c);
}

// Release-ordered ticket increment: makes this thread's prior (atomic) writes
// visible before the increment, WITHOUT a standalone gpu-scope fence (which on
// sm_103a emits CCTL.IVALL and flushes co-resident blocks' L1).
__device__ __forceinline__ unsigned ticket_release_add(unsigned int* p) {
    unsigned old;
    asm volatile("atom.release.gpu.global.add.u32 %0, [%1], 1;"
                 : "=r"(old) : "l"(p) : "memory");
    return old;
}

// Block reduce of (lsum, csum) -> atomicAdd into g_scratch[o_loss], [o_cnt].
__device__ __forceinline__ void reduce_and_accumulate(float lsum, float csum,
                                                      int o_loss, int o_cnt)
{
    __shared__ float rl[16], rc[16];
    int lane = threadIdx.x & 31, warp = threadIdx.x >> 5;
    #pragma unroll
    for (int off = 16; off > 0; off >>= 1) {
        lsum += __shfl_down_sync(0xffffffffu, lsum, off);
        csum += __shfl_down_sync(0xffffffffu, csum, off);
    }
    if (lane == 0) { rl[warp] = lsum; rc[warp] = csum; }
    __syncthreads();
    if (warp == 0) {
        int nw = blockDim.x >> 5;
        lsum = (lane < nw) ? rl[lane] : 0.0f;
        csum = (lane < nw) ? rc[lane] : 0.0f;
        #pragma unroll
        for (int off = 16; off > 0; off >>= 1) {
            lsum += __shfl_down_sync(0xffffffffu, lsum, off);
            csum += __shfl_down_sync(0xffffffffu, csum, off);
        }
        if (lane == 0) {
            atomicAdd(&g_scratch[o_loss], lsum);
            atomicAdd(&g_scratch[o_cnt], csum);
        }
    }
}

// Negative branch for one (b, a, d-tile, h-tile). TW == W (full rows).
// smem holds SUM = 1 + e^{x1-x0} + e^{x2-x0} (log deferred; log monotonic ->
// 3x3x3 max and mp==center identical in sum domain). Halo pad = 0.0f.
template<int TD, int TH, int TW, int D, int H, int W, int A>
__device__ __forceinline__ void neg_level(const float* __restrict__ logit,
                                          const float* __restrict__ prob_gt,
                                          int local)
{
    constexpr int SD = TD + 2, SH = TH + 2;
    constexpr int SWP = (TW + 8 + 3) & ~3;     // 72 (TW=64), 40 (TW=32)
    constexpr int ROWS = SD * SH;
    constexpr int VEC = TW / 4;
    constexpr int ITEMS = ROWS * VEC;
    constexpr int NIT = (ITEMS + 511) / 512;
    constexpr int tilesD = D / TD, tilesH = H / TH;
    constexpr int S = D * H * W;
    constexpr int ODC = TD / 2;                // depth outputs per warp group

    float* s = dynsmem;

    const int baIdx = local / (tilesD * tilesH);
    const int tile  = local % (tilesD * tilesH);
    const int b = baIdx / A, a = baIdx % A;
    const int d0 = (tile / tilesH) * TD;
    const int h0 = (tile % tilesH) * TH;

    const float* l0 = logit + (b * NCLS * A + a) * S;
    const int tid = threadIdx.x;
    const float PAD = 0.0f;

    // ---- Phase 1: sum = 1 + e^{x1-x0} + e^{x2-x0}, float4, static unroll ----
    #pragma unroll
    for (int it = 0; it < NIT; it++) {
        int idx = tid + it * 512;
        if (NIT * 512 == ITEMS || idx < ITEMS) {
            int row = idx / VEC;
            int v   = idx & (VEC - 1);
            int dz = row / SH, hz = row % SH;
            int d = d0 + dz - 1, h = h0 + hz - 1;
            float4 r;
            if ((unsigned)d < (unsigned)D && (unsigned)h < (unsigned)H) {
                int sp = (d * H + h) * W + 4 * v;
                float4 a0 = __ldg((const float4*)(l0 + sp));
                float4 a1 = __ldg((const float4*)(l0 + A * S + sp));
                float4 a2 = __ldg((const float4*)(l0 + 2 * A * S + sp));
                r.x = 1.0f + __expf(a1.x - a0.x) + __expf(a2.x - a0.x);
                r.y = 1.0f + __expf(a1.y - a0.y) + __expf(a2.y - a0.y);
                r.z = 1.0f + __expf(a1.z - a0.z) + __expf(a2.z - a0.z);
                r.w = 1.0f + __expf(a1.w - a0.w) + __expf(a2.w - a0.w);
            } else {
                r.x = r.y = r.z = r.w = PAD;
            }
            *(float4*)(s + row * SWP + 4 + 4 * v) = r;
        }
    }
    __syncthreads();

    // ---- Phase 2: NMS in sum domain + focal neg loss (log deferred) ----
    const int lane = tid & 31, warp = tid >> 5;
    const int ty  = warp & 7;            // TH == 8 always
    const int tz  = warp >> 3;
    const int odb = tz * ODC;

    const float* pg = prob_gt + (b * A + a) * S;
    float lsum = 0.0f, csum = 0.0f;

    if (TW == 64) {
        // Each lane owns a w-pair (cols cp, cp+1) via 64-bit smem accesses.
        const int cp = 4 + 2 * lane;
        auto hw2 = [&](int z) -> float2 {
            const float* p = s + (z * SH + ty) * SWP + cp;
            float2 r0 = *(const float2*)p;
            float2 r1 = *(const float2*)(p + SWP);
            float2 r2 = *(const float2*)(p + 2 * SWP);
            float hx = max3(r0.x, r1.x, r2.x);
            float hy = max3(r0.y, r1.y, r2.y);
            float l = __shfl_up_sync(0xffffffffu, hy, 1);
            float r = __shfl_down_sync(0xffffffffu, hx, 1);
            if (lane == 0)  l = PAD;
            if (lane == 31) r = PAD;
            return make_float2(max3(l, hx, hy), max3(hx, hy, r));
        };
        float2 a0 = hw2(odb), a1 = hw2(odb + 1);
        #pragma unroll
        for (int i = 0; i < ODC; i++) {
            int od = odb + i;
            int gb = ((d0 + od) * H + h0 + ty) * W + cp - 4;
            float2 pgv = __ldg((const float2*)(pg + gb));   // hoisted
            float2 a2 = hw2(od + 2);
            float mpx = max3(a0.x, a1.x, a2.x);
            float mpy = max3(a0.y, a1.y, a2.y);
            float2 cen = *(const float2*)(s + ((od + 1) * SH + ty + 1) * SWP + cp);
            if (mpx == cen.x && pgv.x == -1.0f) {
                float nll = __logf(cen.x);
                float p = __expf(-nll);
                float q = 1.0f - p; float wn = q * q;
                lsum += nll * wn; csum += wn;
            }
            if (mpy == cen.y && pgv.y == -1.0f) {
                float nll = __logf(cen.y);
                float p = __expf(-nll);
                float q = 1.0f - p; float wn = q * q;
                lsum += nll * wn; csum += wn;
            }
            a0 = a1; a1 = a2;
        }
    } else {
        const int ca = 4 + lane;
        auto wm1 = [&](int z) -> float {
            const float* p = s + (z * SH + ty) * SWP + ca;
            float h = max3(p[0], p[SWP], p[2 * SWP]);
            float l = __shfl_up_sync(0xffffffffu, h, 1);
            float r = __shfl_down_sync(0xffffffffu, h, 1);
            if (lane == 0)  l = PAD;
            if (lane == 31) r = PAD;
            return max3(l, h, r);
        };
        float a0 = wm1(odb), a1 = wm1(odb + 1);
        #pragma unroll
        for (int i = 0; i < ODC; i++) {
            int od = odb + i;
            int gb = ((d0 + od) * H + h0 + ty) * W;
            float pga = __ldg(pg + gb + lane);
            float a2 = wm1(od + 2);
            float mp = max3(a0, a1, a2);
            float cen = s[((od + 1) * SH + ty + 1) * SWP + ca];
            if (mp == cen && pga == -1.0f) {
                float nll = __logf(cen);
                float p = __expf(-nll);
                float q = 1.0f - p; float wn = q * q;
                lsum += nll * wn; csum += wn;
            }
            a0 = a1; a1 = a2;
        }
    }
    reduce_and_accumulate(lsum, csum, 1, 3);
}

// Positive branch (one 512-thread block, B*P = 512 points).
__device__ __forceinline__ void pos_level(const float* __restrict__ logit,
                                          const float* __restrict__ prob_gt,
                                          const int* __restrict__ coord,
                                          const float* __restrict__ wcls,
                                          int A, int D, int H, int W, int P)
{
    int idx = threadIdx.x;
    float lsum = 0.0f, csum = 0.0f;
    int b = idx / P;
    int4 c = __ldg((const int4*)coord + idx);
    int a = c.x;
    if (a > -1) {
        int d = c.y, h = c.z, w = c.w;
        int S = D * H * W;
        int sp = (d * H + h) * W + w;
        int cls = (int)__ldg(prob_gt + (b * A + a) * S + sp);
        const float* lb = logit + (b * NCLS * A + a) * S + sp;
        float x0 = __ldg(lb);
        float x1 = __ldg(lb + A * S);
        float x2 = __ldg(lb + 2 * A * S);
        float m = fmaxf(x0, fmaxf(x1, x2));
        float lse = m + __logf(__expf(x0 - m) + __expf(x1 - m) + __expf(x2 - m));
        float xc = (cls == 0) ? x0 : ((cls == 1) ? x1 : x2);
        float nll = lse - xc;
        float pt = __expf(-nll);
        float q = 1.0f - pt;
        float wp = q * q * __ldg(wcls + cls);
        lsum = nll * wp;
        csum = wp;
    }
    __syncthreads();
    reduce_and_accumulate(lsum, csum, 0, 2);
}

// Blocks 0..383: level0 neg (16x8x64). 384..431: level1 neg (32x8x32 full-depth).
// Blocks 432, 433: positive branch. 434 <= 444 = 3*148 -> balanced single wave.
// Last finishing block copies g_scratch -> out and resets scratch (graph-safe).
// The ticket increment carries release semantics; scratch reads are atomics
// (L2-direct), so no gpu-scope fence (and no CCTL.IVALL L1 flush) is needed.
__global__ void __launch_bounds__(512, 3)
mega_kernel(const float* __restrict__ logit0, const float* __restrict__ logit1,
            const float* __restrict__ pg0, const float* __restrict__ pg1,
            const int* __restrict__ c0, const int* __restrict__ c1,
            const float* __restrict__ wcls, float* __restrict__ out)
{
    int bx = blockIdx.x;
    if (bx < 384) {
        neg_level<16, 8, 64, 64, 64, 64, 3>(logit0, pg0, bx);
    } else if (bx < 432) {
        neg_level<32, 8, 32, 32, 32, 32, 3>(logit1, pg1, bx - 384);
    } else if (bx == 432) {
        pos_level(logit0, pg0, c0, wcls, 3, 64, 64, 64, 128);
    } else {
        pos_level(logit1, pg1, c1, wcls, 3, 32, 32, 32, 128);
    }

    // Finalize: tid 0 issued this block's scratch atomics (warp 0 lane 0),
    // so same-thread release ordering on the ticket suffices.
    if (threadIdx.x == 0) {
        unsigned t = ticket_release_add(&g_ticket);
        if (t == NBLOCKS - 1) {
            #pragma unroll
            for (int i = 0; i < 4; i++) {
                out[i] = atomicExch(&g_scratch[i], 0.0f);
            }
            atomicExch(&g_ticket, 0u);
        }
    }
}

extern "C" void kernel_launch(void* const* d_in, const int* in_sizes, int n_in,
                              void* d_out, int out_size)
{
    const float* logit0 = (const float*)d_in[0];
    const float* logit1 = (const float*)d_in[1];
    const float* pg0    = (const float*)d_in[2];
    const float* pg1    = (const float*)d_in[3];
    const int*   c0     = (const int*)d_in[4];
    const int*   c1     = (const int*)d_in[5];
    const float* wcls   = (const float*)d_in[6];
    float* out = (float*)d_out;

    // smem: max(level0 18*10*72, level1 34*10*40) floats = 13600 * 4 = 54400 B
    constexpr int SMEM_BYTES = 34 * 10 * 40 * 4;
    static bool attr_set = false;
    if (!attr_set) {
        cudaFuncSetAttribute(mega_kernel,
                             cudaFuncAttributeMaxDynamicSharedMemorySize,
                             SMEM_BYTES);
        attr_set = true;
    }

    mega_kernel<<<NBLOCKS, 512, SMEM_BYTES>>>(logit0, logit1, pg0, pg1,
                                              c0, c1, wcls, out);
}

// round 13
// speedup vs baseline: 1.0152x; 1.0019x over previous
#include <cuda_runtime.h>
#include <math_constants.h>

#define NCLS 3

extern __shared__ float dynsmem[];

__global__ void init_out_kernel(float* __restrict__ out) {
    if (threadIdx.x < 4) out[threadIdx.x] = 0.0f;
}

__device__ __forceinline__ float max3(float a, float b, float c) {
    return fmaxf(fmaxf(a, b), c);
}

__device__ __forceinline__ void reduce_and_accumulate(float lsum, float csum,
                                                      float* __restrict__ out,
                                                      int o_loss, int o_cnt)
{
    __shared__ float rl[16], rc[16];
    int lane = threadIdx.x & 31, warp = threadIdx.x >> 5;
    #pragma unroll
    for (int off = 16; off > 0; off >>= 1) {
        lsum += __shfl_down_sync(0xffffffffu, lsum, off);
        csum += __shfl_down_sync(0xffffffffu, csum, off);
    }
    if (lane == 0) { rl[warp] = lsum; rc[warp] = csum; }
    __syncthreads();
    if (warp == 0) {
        int nw = blockDim.x >> 5;
        lsum = (lane < nw) ? rl[lane] : 0.0f;
        csum = (lane < nw) ? rc[lane] : 0.0f;
        #pragma unroll
        for (int off = 16; off > 0; off >>= 1) {
            lsum += __shfl_down_sync(0xffffffffu, lsum, off);
            csum += __shfl_down_sync(0xffffffffu, csum, off);
        }
        if (lane == 0) {
            atomicAdd(&out[o_loss], lsum);
            atomicAdd(&out[o_cnt], csum);
        }
    }
}

// Negative branch for one (b, a, d-tile, h-tile). TW == W (full rows).
// smem holds SUM = 1 + e^{x1-x0} + e^{x2-x0} (log deferred; log monotonic ->
// 3x3x3 max and mp==center identical in sum domain). Halo pad = 0.0f.
// prob_neg = exp(-nll) = 1/sum -> computed as __frcp_rn(sum), independent of
// the __logf on the critical path.
template<int TD, int TH, int TW, int D, int H, int W, int A>
__device__ __forceinline__ void neg_level(const float* __restrict__ logit,
                                          const float* __restrict__ prob_gt,
                                          float* __restrict__ out,
                                          int local)
{
    constexpr int SD = TD + 2, SH = TH + 2;
    constexpr int SWP = (TW + 8 + 3) & ~3;     // 72 (TW=64), 40 (TW=32)
    constexpr int ROWS = SD * SH;
    constexpr int VEC = TW / 4;
    constexpr int ITEMS = ROWS * VEC;
    constexpr int NIT = (ITEMS + 511) / 512;
    constexpr int tilesD = D / TD, tilesH = H / TH;
    constexpr int S = D * H * W;
    constexpr int ODC = TD / 2;                // depth outputs per warp group

    float* s = dynsmem;

    const int baIdx = local / (tilesD * tilesH);
    const int tile  = local % (tilesD * tilesH);
    const int b = baIdx / A, a = baIdx % A;
    const int d0 = (tile / tilesH) * TD;
    const int h0 = (tile % tilesH) * TH;

    const float* l0 = logit + (b * NCLS * A + a) * S;
    const int tid = threadIdx.x;
    const float PAD = 0.0f;

    // ---- Phase 1: sum = 1 + e^{x1-x0} + e^{x2-x0}, float4, static unroll ----
    #pragma unroll
    for (int it = 0; it < NIT; it++) {
        int idx = tid + it * 512;
        if (NIT * 512 == ITEMS || idx < ITEMS) {
            int row = idx / VEC;
            int v   = idx & (VEC - 1);
            int dz = row / SH, hz = row % SH;
            int d = d0 + dz - 1, h = h0 + hz - 1;
            float4 r;
            if ((unsigned)d < (unsigned)D && (unsigned)h < (unsigned)H) {
                int sp = (d * H + h) * W + 4 * v;
                float4 a0 = __ldg((const float4*)(l0 + sp));
                float4 a1 = __ldg((const float4*)(l0 + A * S + sp));
                float4 a2 = __ldg((const float4*)(l0 + 2 * A * S + sp));
                r.x = 1.0f + __expf(a1.x - a0.x) + __expf(a2.x - a0.x);
                r.y = 1.0f + __expf(a1.y - a0.y) + __expf(a2.y - a0.y);
                r.z = 1.0f + __expf(a1.z - a0.z) + __expf(a2.z - a0.z);
                r.w = 1.0f + __expf(a1.w - a0.w) + __expf(a2.w - a0.w);
            } else {
                r.x = r.y = r.z = r.w = PAD;
            }
            *(float4*)(s + row * SWP + 4 + 4 * v) = r;
        }
    }
    __syncthreads();

    // ---- Phase 2: NMS in sum domain + focal neg loss (log deferred) ----
    const int lane = tid & 31, warp = tid >> 5;
    const int ty  = warp & 7;            // TH == 8 always
    const int tz  = warp >> 3;
    const int odb = tz * ODC;

    const float* pg = prob_gt + (b * A + a) * S;
    float lsum = 0.0f, csum = 0.0f;

    if (TW == 64) {
        // Each lane owns a w-pair (cols cp, cp+1) via 64-bit smem accesses.
        const int cp = 4 + 2 * lane;
        auto hw2 = [&](int z) -> float2 {
            const float* p = s + (z * SH + ty) * SWP + cp;
            float2 r0 = *(const float2*)p;
            float2 r1 = *(const float2*)(p + SWP);
            float2 r2 = *(const float2*)(p + 2 * SWP);
            float hx = max3(r0.x, r1.x, r2.x);
            float hy = max3(r0.y, r1.y, r2.y);
            float l = __shfl_up_sync(0xffffffffu, hy, 1);
            float r = __shfl_down_sync(0xffffffffu, hx, 1);
            if (lane == 0)  l = PAD;
            if (lane == 31) r = PAD;
            return make_float2(max3(l, hx, hy), max3(hx, hy, r));
        };
        float2 a0 = hw2(odb), a1 = hw2(odb + 1);
        #pragma unroll
        for (int i = 0; i < ODC; i++) {
            int od = odb + i;
            int gb = ((d0 + od) * H + h0 + ty) * W + cp - 4;
            float2 pgv = __ldg((const float2*)(pg + gb));   // hoisted
            float2 a2 = hw2(od + 2);
            float mpx = max3(a0.x, a1.x, a2.x);
            float mpy = max3(a0.y, a1.y, a2.y);
            float2 cen = *(const float2*)(s + ((od + 1) * SH + ty + 1) * SWP + cp);
            if (mpx == cen.x && pgv.x == -1.0f) {
                float nll = __logf(cen.x);
                float p = __frcp_rn(cen.x);     // exp(-log(sum)) = 1/sum
                float q = 1.0f - p; float wn = q * q;
                lsum += nll * wn; csum += wn;
            }
            if (mpy == cen.y && pgv.y == -1.0f) {
                float nll = __logf(cen.y);
                float p = __frcp_rn(cen.y);
                float q = 1.0f - p; float wn = q * q;
                lsum += nll * wn; csum += wn;
            }
            a0 = a1; a1 = a2;
        }
    } else {
        const int ca = 4 + lane;
        auto wm1 = [&](int z) -> float {
            const float* p = s + (z * SH + ty) * SWP + ca;
            float h = max3(p[0], p[SWP], p[2 * SWP]);
            float l = __shfl_up_sync(0xffffffffu, h, 1);
            float r = __shfl_down_sync(0xffffffffu, h, 1);
            if (lane == 0)  l = PAD;
            if (lane == 31) r = PAD;
            return max3(l, h, r);
        };
        float a0 = wm1(odb), a1 = wm1(odb + 1);
        #pragma unroll
        for (int i = 0; i < ODC; i++) {
            int od = odb + i;
            int gb = ((d0 + od) * H + h0 + ty) * W;
            float pga = __ldg(pg + gb + lane);
            float a2 = wm1(od + 2);
            float mp = max3(a0, a1, a2);
            float cen = s[((od + 1) * SH + ty + 1) * SWP + ca];
            if (mp == cen && pga == -1.0f) {
                float nll = __logf(cen);
                float p = __frcp_rn(cen);
                float q = 1.0f - p; float wn = q * q;
                lsum += nll * wn; csum += wn;
            }
            a0 = a1; a1 = a2;
        }
    }
    reduce_and_accumulate(lsum, csum, out, 1, 3);
}

// Positive branch (one 512-thread block, B*P = 512 points).
__device__ __forceinline__ void pos_level(const float* __restrict__ logit,
                                          const float* __restrict__ prob_gt,
                                          const int* __restrict__ coord,
                                          const float* __restrict__ wcls,
                                          float* __restrict__ out,
                                          int A, int D, int H, int W, int P)
{
    int idx = threadIdx.x;
    float lsum = 0.0f, csum = 0.0f;
    int b = idx / P;
    int4 c = __ldg((const int4*)coord + idx);
    int a = c.x;
    if (a > -1) {
        int d = c.y, h = c.z, w = c.w;
        int S = D * H * W;
        int sp = (d * H + h) * W + w;
        int cls = (int)__ldg(prob_gt + (b * A + a) * S + sp);
        const float* lb = logit + (b * NCLS * A + a) * S + sp;
        float x0 = __ldg(lb);
        float x1 = __ldg(lb + A * S);
        float x2 = __ldg(lb + 2 * A * S);
        float m = fmaxf(x0, fmaxf(x1, x2));
        float lse = m + __logf(__expf(x0 - m) + __expf(x1 - m) + __expf(x2 - m));
        float xc = (cls == 0) ? x0 : ((cls == 1) ? x1 : x2);
        float nll = lse - xc;
        float pt = __expf(-nll);
        float q = 1.0f - pt;
        float wp = q * q * __ldg(wcls + cls);
        lsum = nll * wp;
        csum = wp;
    }
    __syncthreads();
    reduce_and_accumulate(lsum, csum, out, 0, 2);
}

// Blocks 0..383: level0 neg (16x8x64). 384..431: level1 neg (32x8x32 full-depth).
// Blocks 432, 433: positive branch. 434 <= 444 = 3*148 -> balanced single wave.
__global__ void __launch_bounds__(512, 3)
mega_kernel(const float* __restrict__ logit0, const float* __restrict__ logit1,
            const float* __restrict__ pg0, const float* __restrict__ pg1,
            const int* __restrict__ c0, const int* __restrict__ c1,
            const float* __restrict__ wcls, float* __restrict__ out)
{
    int bx = blockIdx.x;
    if (bx < 384) {
        neg_level<16, 8, 64, 64, 64, 64, 3>(logit0, pg0, out, bx);
    } else if (bx < 432) {
        neg_level<32, 8, 32, 32, 32, 32, 3>(logit1, pg1, out, bx - 384);
    } else if (bx == 432) {
        pos_level(logit0, pg0, c0, wcls, out, 3, 64, 64, 64, 128);
    } else {
        pos_level(logit1, pg1, c1, wcls, out, 3, 32, 32, 32, 128);
    }
}

extern "C" void kernel_launch(void* const* d_in, const int* in_sizes, int n_in,
                              void* d_out, int out_size)
{
    const float* logit0 = (const float*)d_in[0];
    const float* logit1 = (const float*)d_in[1];
    const float* pg0    = (const float*)d_in[2];
    const float* pg1    = (const float*)d_in[3];
    const int*   c0     = (const int*)d_in[4];
    const int*   c1     = (const int*)d_in[5];
    const float* wcls   = (const float*)d_in[6];
    float* out = (float*)d_out;

    // smem: max(level0 18*10*72, level1 34*10*40) floats = 13600 * 4 = 54400 B
    constexpr int SMEM_BYTES = 34 * 10 * 40 * 4;
    static bool attr_set = false;
    if (!attr_set) {
        cudaFuncSetAttribute(mega_kernel,
                             cudaFuncAttributeMaxDynamicSharedMemorySize,
                             SMEM_BYTES);
        attr_set = true;
    }

    init_out_kernel<<<1, 32>>>(out);
    mega_kernel<<<434, 512, SMEM_BYTES>>>(logit0, logit1, pg0, pg1,
                                          c0, c1, wcls, out);
}

// round 14
// speedup vs baseline: 1.1380x; 1.1210x over previous
#include <cuda_runtime.h>
#include <math_constants.h>

#define NCLS 3

extern __shared__ float dynsmem[];

__global__ void init_out_kernel(float* __restrict__ out) {
    if (threadIdx.x < 4) out[threadIdx.x] = 0.0f;
}

__device__ __forceinline__ float max3(float a, float b, float c) {
    return fmaxf(fmaxf(a, b), c);
}

__device__ __forceinline__ void reduce_and_accumulate(float lsum, float csum,
                                                      float* __restrict__ out,
                                                      int o_loss, int o_cnt)
{
    __shared__ float rl[16], rc[16];
    int lane = threadIdx.x & 31, warp = threadIdx.x >> 5;
    #pragma unroll
    for (int off = 16; off > 0; off >>= 1) {
        lsum += __shfl_down_sync(0xffffffffu, lsum, off);
        csum += __shfl_down_sync(0xffffffffu, csum, off);
    }
    if (lane == 0) { rl[warp] = lsum; rc[warp] = csum; }
    __syncthreads();
    if (warp == 0) {
        int nw = blockDim.x >> 5;
        lsum = (lane < nw) ? rl[lane] : 0.0f;
        csum = (lane < nw) ? rc[lane] : 0.0f;
        #pragma unroll
        for (int off = 16; off > 0; off >>= 1) {
            lsum += __shfl_down_sync(0xffffffffu, lsum, off);
            csum += __shfl_down_sync(0xffffffffu, csum, off);
        }
        if (lane == 0) {
            atomicAdd(&out[o_loss], lsum);
            atomicAdd(&out[o_cnt], csum);
        }
    }
}

// Negative branch for one (b, a, d-tile, h-tile). TW == W (full rows).
// smem holds SUM = 1 + e^{x1-x0} + e^{x2-x0} (log deferred; log monotonic ->
// 3x3x3 max and mp==center identical in sum domain). Halo pad = 0.0f.
template<int TD, int TH, int TW, int D, int H, int W, int A>
__device__ __forceinline__ void neg_level(const float* __restrict__ logit,
                                          const float* __restrict__ prob_gt,
                                          float* __restrict__ out,
                                          int local)
{
    constexpr int SD = TD + 2, SH = TH + 2;
    constexpr int SWP = (TW + 8 + 3) & ~3;     // 72 (TW=64), 40 (TW=32)
    constexpr int ROWS = SD * SH;
    constexpr int VEC = TW / 4;
    constexpr int ITEMS = ROWS * VEC;
    constexpr int NIT = (ITEMS + 511) / 512;
    constexpr int tilesD = D / TD, tilesH = H / TH;
    constexpr int S = D * H * W;
    constexpr int ODC = TD / 2;                // depth outputs per warp group

    float* s = dynsmem;

    const int baIdx = local / (tilesD * tilesH);
    const int tile  = local % (tilesD * tilesH);
    const int b = baIdx / A, a = baIdx % A;
    const int d0 = (tile / tilesH) * TD;
    const int h0 = (tile % tilesH) * TH;

    const float* l0 = logit + (b * NCLS * A + a) * S;
    const int tid = threadIdx.x;
    const float PAD = 0.0f;

    // ---- Phase 1: sum = 1 + e^{x1-x0} + e^{x2-x0}, float4, static unroll ----
    #pragma unroll
    for (int it = 0; it < NIT; it++) {
        int idx = tid + it * 512;
        if (NIT * 512 == ITEMS || idx < ITEMS) {
            int row = idx / VEC;
            int v   = idx & (VEC - 1);
            int dz = row / SH, hz = row % SH;
            int d = d0 + dz - 1, h = h0 + hz - 1;
            float4 r;
            if ((unsigned)d < (unsigned)D && (unsigned)h < (unsigned)H) {
                int sp = (d * H + h) * W + 4 * v;
                float4 a0 = __ldg((const float4*)(l0 + sp));
                float4 a1 = __ldg((const float4*)(l0 + A * S + sp));
                float4 a2 = __ldg((const float4*)(l0 + 2 * A * S + sp));
                r.x = 1.0f + __expf(a1.x - a0.x) + __expf(a2.x - a0.x);
                r.y = 1.0f + __expf(a1.y - a0.y) + __expf(a2.y - a0.y);
                r.z = 1.0f + __expf(a1.z - a0.z) + __expf(a2.z - a0.z);
                r.w = 1.0f + __expf(a1.w - a0.w) + __expf(a2.w - a0.w);
            } else {
                r.x = r.y = r.z = r.w = PAD;
            }
            *(float4*)(s + row * SWP + 4 + 4 * v) = r;
        }
    }
    __syncthreads();

    // ---- Phase 2: NMS in sum domain + focal neg loss (log deferred) ----
    const int lane = tid & 31, warp = tid >> 5;
    const int ty  = warp & 7;            // TH == 8 always
    const int tz  = warp >> 3;
    const int odb = tz * ODC;

    const float* pg = prob_gt + (b * A + a) * S;
    float lsum = 0.0f, csum = 0.0f;

    if (TW == 64) {
        // Each lane owns a w-pair (cols cp, cp+1) via 64-bit smem accesses.
        const int cp = 4 + 2 * lane;
        auto hw2 = [&](int z) -> float2 {
            const float* p = s + (z * SH + ty) * SWP + cp;
            float2 r0 = *(const float2*)p;
            float2 r1 = *(const float2*)(p + SWP);
            float2 r2 = *(const float2*)(p + 2 * SWP);
            float hx = max3(r0.x, r1.x, r2.x);
            float hy = max3(r0.y, r1.y, r2.y);
            float l = __shfl_up_sync(0xffffffffu, hy, 1);
            float r = __shfl_down_sync(0xffffffffu, hx, 1);
            if (lane == 0)  l = PAD;
            if (lane == 31) r = PAD;
            return make_float2(max3(l, hx, hy), max3(hx, hy, r));
        };
        float2 a0 = hw2(odb), a1 = hw2(odb + 1);
        #pragma unroll
        for (int i = 0; i < ODC; i++) {
            int od = odb + i;
            int gb = ((d0 + od) * H + h0 + ty) * W + cp - 4;
            float2 pgv = __ldg((const float2*)(pg + gb));   // hoisted
            float2 a2 = hw2(od + 2);
            float mpx = max3(a0.x, a1.x, a2.x);
            float mpy = max3(a0.y, a1.y, a2.y);
            float2 cen = *(const float2*)(s + ((od + 1) * SH + ty + 1) * SWP + cp);
            if (mpx == cen.x && pgv.x == -1.0f) {
                float nll = __logf(cen.x);
                float p = __expf(-nll);
                float q = 1.0f - p; float wn = q * q;
                lsum += nll * wn; csum += wn;
            }
            if (mpy == cen.y && pgv.y == -1.0f) {
                float nll = __logf(cen.y);
                float p = __expf(-nll);
                float q = 1.0f - p; float wn = q * q;
                lsum += nll * wn; csum += wn;
            }
            a0 = a1; a1 = a2;
        }
    } else {
        const int ca = 4 + lane;
        auto wm1 = [&](int z) -> float {
            const float* p = s + (z * SH + ty) * SWP + ca;
            float h = max3(p[0], p[SWP], p[2 * SWP]);
            float l = __shfl_up_sync(0xffffffffu, h, 1);
            float r = __shfl_down_sync(0xffffffffu, h, 1);
            if (lane == 0)  l = PAD;
            if (lane == 31) r = PAD;
            return max3(l, h, r);
        };
        float a0 = wm1(odb), a1 = wm1(odb + 1);
        #pragma unroll
        for (int i = 0; i < ODC; i++) {
            int od = odb + i;
            int gb = ((d0 + od) * H + h0 + ty) * W;
            float pga = __ldg(pg + gb + lane);
            float a2 = wm1(od + 2);
            float mp = max3(a0, a1, a2);
            float cen = s[((od + 1) * SH + ty + 1) * SWP + ca];
            if (mp == cen && pga == -1.0f) {
                float nll = __logf(cen);
                float p = __expf(-nll);
                float q = 1.0f - p; float wn = q * q;
                lsum += nll * wn; csum += wn;
            }
            a0 = a1; a1 = a2;
        }
    }
    reduce_and_accumulate(lsum, csum, out, 1, 3);
}

// Positive branch (one 512-thread block, B*P = 512 points).
__device__ __forceinline__ void pos_level(const float* __restrict__ logit,
                                          const float* __restrict__ prob_gt,
                                          const int* __restrict__ coord,
                                          const float* __restrict__ wcls,
                                          float* __restrict__ out,
                                          int A, int D, int H, int W, int P)
{
    int idx = threadIdx.x;
    float lsum = 0.0f, csum = 0.0f;
    int b = idx / P;
    const int* c = coord + idx * 4;
    int a = c[0];
    if (a > -1) {
        int d = c[1], h = c[2], w = c[3];
        int S = D * H * W;
        int sp = (d * H + h) * W + w;
        int cls = (int)__ldg(prob_gt + (b * A + a) * S + sp);
        const float* lb = logit + (b * NCLS * A + a) * S + sp;
        float x0 = __ldg(lb);
        float x1 = __ldg(lb + A * S);
        float x2 = __ldg(lb + 2 * A * S);
        float m = fmaxf(x0, fmaxf(x1, x2));
        float lse = m + __logf(__expf(x0 - m) + __expf(x1 - m) + __expf(x2 - m));
        float xc = (cls == 0) ? x0 : ((cls == 1) ? x1 : x2);
        float nll = lse - xc;
        float pt = __expf(-nll);
        float q = 1.0f - pt;
        float wp = q * q * __ldg(wcls + cls);
        lsum = nll * wp;
        csum = wp;
    }
    __syncthreads();
    reduce_and_accumulate(lsum, csum, out, 0, 2);
}

// Blocks 0..383: level0 neg (16x8x64). 384..431: level1 neg (32x8x32 full-depth).
// Blocks 432, 433: positive branch. 434 blocks <= 444 = 3*148 -> balanced wave.
__global__ void __launch_bounds__(512, 3)
mega_kernel(const float* __restrict__ logit0, const float* __restrict__ logit1,
            const float* __restrict__ pg0, const float* __restrict__ pg1,
            const int* __restrict__ c0, const int* __restrict__ c1,
            const float* __restrict__ wcls, float* __restrict__ out)
{
    int bx = blockIdx.x;
    if (bx < 384) {
        neg_level<16, 8, 64, 64, 64, 64, 3>(logit0, pg0, out, bx);
    } else if (bx < 432) {
        neg_level<32, 8, 32, 32, 32, 32, 3>(logit1, pg1, out, bx - 384);
    } else if (bx == 432) {
        pos_level(logit0, pg0, c0, wcls, out, 3, 64, 64, 64, 128);
    } else {
        pos_level(logit1, pg1, c1, wcls, out, 3, 32, 32, 32, 128);
    }
}

extern "C" void kernel_launch(void* const* d_in, const int* in_sizes, int n_in,
                              void* d_out, int out_size)
{
    const float* logit0 = (const float*)d_in[0];
    const float* logit1 = (const float*)d_in[1];
    const float* pg0    = (const float*)d_in[2];
    const float* pg1    = (const float*)d_in[3];
    const int*   c0     = (const int*)d_in[4];
    const int*   c1     = (const int*)d_in[5];
    const float* wcls   = (const float*)d_in[6];
    float* out = (float*)d_out;

    // smem: max(level0 18*10*72, level1 34*10*40) floats = 13600 * 4 = 54400 B
    constexpr int SMEM_BYTES = 34 * 10 * 40 * 4;
    static bool attr_set = false;
    if (!attr_set) {
        cudaFuncSetAttribute(mega_kernel,
                             cudaFuncAttributeMaxDynamicSharedMemorySize,
                             SMEM_BYTES);
        attr_set = true;
    }

    init_out_kernel<<<1, 32>>>(out);
    mega_kernel<<<434, 512, SMEM_BYTES>>>(logit0, logit1, pg0, pg1,
                                          c0, c1, wcls, out);
}